// round 6
// baseline (speedup 1.0000x reference)
#include <cuda_runtime.h>
#include <cuda_fp16.h>

#define NUM_USERS 50000
#define NUM_ITEMS 100000
#define NUM_NODES 150000   // NUM_USERS + NUM_ITEMS
#define LATENT_DIM 64
#define NNZ 4800000
#define BATCH 4096

// Scratch state (allocation-free, graph-capturable).
// Propagation buffers are fp16 (128B/row) to halve L2 gather traffic;
// the LightGCN accumulator stays fp32.
struct Half8 { __half2 a, b, c, d; };          // 16 bytes = 8 halfs

__device__ Half8 g_hA[NUM_NODES * LATENT_DIM / 8];
__device__ Half8 g_hB[NUM_NODES * LATENT_DIM / 8];
__device__ float g_acc[NUM_NODES * LATENT_DIM];
__device__ int   g_row_ptr[NUM_NODES + 1];

// ---------------------------------------------------------------------------
// Init: concat(user_emb, item_emb) -> g_hA (half, cur) and g_acc (fp32).
// One thread per 8 dims (16B half / 32B float).
// ---------------------------------------------------------------------------
__global__ void __launch_bounds__(256) init_kernel(const float4* __restrict__ user_emb,
                                                   const float4* __restrict__ item_emb)
{
    const int total  = NUM_NODES * LATENT_DIM / 8;   // Half8 count
    const int uocts  = NUM_USERS * LATENT_DIM / 8;
    int i = blockIdx.x * blockDim.x + threadIdx.x;
    if (i >= total) return;

    const float4* src = (i < uocts) ? (user_emb + (size_t)i * 2)
                                    : (item_emb + (size_t)(i - uocts) * 2);
    float4 v0 = __ldg(&src[0]);
    float4 v1 = __ldg(&src[1]);

    reinterpret_cast<float4*>(g_acc)[(size_t)i * 2 + 0] = v0;
    reinterpret_cast<float4*>(g_acc)[(size_t)i * 2 + 1] = v1;

    Half8 h;
    h.a = __floats2half2_rn(v0.x, v0.y);
    h.b = __floats2half2_rn(v0.z, v0.w);
    h.c = __floats2half2_rn(v1.x, v1.y);
    h.d = __floats2half2_rn(v1.z, v1.w);
    g_hA[i] = h;
}

// ---------------------------------------------------------------------------
// Build CSR row_ptr from sorted edge_rows.
// ---------------------------------------------------------------------------
__global__ void __launch_bounds__(256) rowptr_kernel(const int* __restrict__ rows)
{
    int e = blockIdx.x * blockDim.x + threadIdx.x;
    if (e >= NNZ) return;
    int r  = rows[e];
    int rp = (e == 0) ? -1 : rows[e - 1];
    for (int rr = rp + 1; rr <= r; ++rr) g_row_ptr[rr] = e;
    if (e == NNZ - 1) {
        for (int rr = r + 1; rr <= NUM_NODES; ++rr) g_row_ptr[rr] = NNZ;
    }
}

// ---------------------------------------------------------------------------
// SpMM (fp16 gather, fp32 accumulate): warp per row.
// Quarter-warp per edge: 4 edges in parallel, each 8 lanes x one Half8
// (16B LDG.128) = full 128B row per edge. Inner loop: 8 edges/iter,
// two load streams, two fp32 accumulator sets of 8.
// Edge metadata staged coalesced (one (col,val) per lane per 32-edge chunk)
// and distributed by shfl; all shfls unconditional, out-of-range vals
// zeroed after the shfl (covers tail and the &31 wraparound).
// ---------------------------------------------------------------------------
__global__ void __launch_bounds__(256) spmm_kernel(const int*   __restrict__ cols,
                                                   const float* __restrict__ vals,
                                                   int flip)
{
    const Half8* __restrict__ xin  = flip ? g_hB : g_hA;
    Half8*       __restrict__ xout = flip ? g_hA : g_hB;

    const unsigned FULL = 0xffffffffu;
    int warp = (blockIdx.x * blockDim.x + threadIdx.x) >> 5;
    int lane = threadIdx.x & 31;
    if (warp >= NUM_NODES) return;

    const int start = g_row_ptr[warp];
    const int end   = g_row_ptr[warp + 1];

    const int sub = lane >> 3;      // edge slot 0..3 within a group of 4
    const int q   = lane & 7;       // Half8 chunk within the 128B row

    const Half8* __restrict__ xq = xin + q;    // lane-fixed column

    float s0[8], s1[8];
    #pragma unroll
    for (int k = 0; k < 8; ++k) { s0[k] = 0.f; s1[k] = 0.f; }

    for (int base = start; base < end; base += 32) {
        const int n = min(32, end - base);      // warp-uniform
        int   c = 0;
        float v = 0.f;
        if (lane < n) {
            c = __ldg(&cols[base + lane]);
            v = __ldg(&vals[base + lane]);
        }

        for (int j = 0; j < n; j += 8) {        // warp-uniform loop
            const int e0 = j + sub;             // edges j..j+3
            const int e1 = j + 4 + sub;         // edges j+4..j+7

            int   cc0 = __shfl_sync(FULL, c, e0 & 31);
            int   cc1 = __shfl_sync(FULL, c, e1 & 31);
            float vv0 = __shfl_sync(FULL, v, e0 & 31);
            float vv1 = __shfl_sync(FULL, v, e1 & 31);
            if (e0 >= n) vv0 = 0.f;
            if (e1 >= n) vv1 = 0.f;

            Half8 x0 = xq[(size_t)cc0 * 8];
            Half8 x1 = xq[(size_t)cc1 * 8];

            {
                float2 f0 = __half22float2(x0.a);
                float2 f1 = __half22float2(x0.b);
                float2 f2 = __half22float2(x0.c);
                float2 f3 = __half22float2(x0.d);
                s0[0] += vv0 * f0.x;  s0[1] += vv0 * f0.y;
                s0[2] += vv0 * f1.x;  s0[3] += vv0 * f1.y;
                s0[4] += vv0 * f2.x;  s0[5] += vv0 * f2.y;
                s0[6] += vv0 * f3.x;  s0[7] += vv0 * f3.y;
            }
            {
                float2 f0 = __half22float2(x1.a);
                float2 f1 = __half22float2(x1.b);
                float2 f2 = __half22float2(x1.c);
                float2 f3 = __half22float2(x1.d);
                s1[0] += vv1 * f0.x;  s1[1] += vv1 * f0.y;
                s1[2] += vv1 * f1.x;  s1[3] += vv1 * f1.y;
                s1[4] += vv1 * f2.x;  s1[5] += vv1 * f2.y;
                s1[6] += vv1 * f3.x;  s1[7] += vv1 * f3.y;
            }
        }
    }

    // combine load streams, then reduce the 4 edge-slots (same q) together
    #pragma unroll
    for (int k = 0; k < 8; ++k) {
        float s = s0[k] + s1[k];
        s += __shfl_xor_sync(FULL, s, 8);
        s += __shfl_xor_sync(FULL, s, 16);
        s0[k] = s;     // all lanes now hold the row sum for dims q*8+k
    }

    if (sub == 0) {
        // pack 8 fp32 -> Half8 -> one 16B store; 8 lanes cover the 128B row
        Half8 h;
        h.a = __floats2half2_rn(s0[0], s0[1]);
        h.b = __floats2half2_rn(s0[2], s0[3]);
        h.c = __floats2half2_rn(s0[4], s0[5]);
        h.d = __floats2half2_rn(s0[6], s0[7]);
        xout[(size_t)warp * 8 + q] = h;
    } else if (sub == 2) {
        // acc += cur, first float4 of this lane's 8 dims
        float4* accp = reinterpret_cast<float4*>(g_acc) + (size_t)warp * 16 + q * 2;
        float4 a = *accp;
        a.x += s0[0]; a.y += s0[1]; a.z += s0[2]; a.w += s0[3];
        *accp = a;
    } else if (sub == 3) {
        // acc += cur, second float4
        float4* accp = reinterpret_cast<float4*>(g_acc) + (size_t)warp * 16 + q * 2 + 1;
        float4 a = *accp;
        a.x += s0[4]; a.y += s0[5]; a.z += s0[6]; a.w += s0[7];
        *accp = a;
    }
}

// ---------------------------------------------------------------------------
// Final: gamma[b] = dot(acc[users[b]], acc[NUM_USERS+items[b]]) / 16
// ---------------------------------------------------------------------------
__global__ void __launch_bounds__(256) dot_kernel(const int* __restrict__ users,
                                                  const int* __restrict__ items,
                                                  float* __restrict__ out)
{
    int warp = (blockIdx.x * blockDim.x + threadIdx.x) >> 5;
    int lane = threadIdx.x & 31;
    if (warp >= BATCH) return;

    size_t u  = (size_t)users[warp];
    size_t it = (size_t)items[warp] + NUM_USERS;

    const float2* au = reinterpret_cast<const float2*>(g_acc + u  * LATENT_DIM);
    const float2* ai = reinterpret_cast<const float2*>(g_acc + it * LATENT_DIM);

    float2 a = au[lane];
    float2 b = ai[lane];
    float s = a.x * b.x + a.y * b.y;

    #pragma unroll
    for (int o = 16; o > 0; o >>= 1)
        s += __shfl_xor_sync(0xffffffffu, s, o);

    if (lane == 0) out[warp] = s * (1.0f / 16.0f);
}

// ---------------------------------------------------------------------------
extern "C" void kernel_launch(void* const* d_in, const int* in_sizes, int n_in,
                              void* d_out, int out_size)
{
    const float* user_emb  = (const float*)d_in[0];
    const float* item_emb  = (const float*)d_in[1];
    const int*   edge_rows = (const int*)  d_in[2];
    const int*   edge_cols = (const int*)  d_in[3];
    const float* edge_vals = (const float*)d_in[4];
    const int*   users     = (const int*)  d_in[5];
    const int*   items     = (const int*)  d_in[6];
    float*       out       = (float*)d_out;

    (void)in_sizes; (void)n_in; (void)out_size;

    {
        int total = NUM_NODES * LATENT_DIM / 8;
        init_kernel<<<(total + 255) / 256, 256>>>(
            reinterpret_cast<const float4*>(user_emb),
            reinterpret_cast<const float4*>(item_emb));
    }

    rowptr_kernel<<<(NNZ + 255) / 256, 256>>>(edge_rows);

    {
        int blocks = (NUM_NODES * 32 + 255) / 256;   // warp per row
        spmm_kernel<<<blocks, 256>>>(edge_cols, edge_vals, 0);
        spmm_kernel<<<blocks, 256>>>(edge_cols, edge_vals, 1);
        spmm_kernel<<<blocks, 256>>>(edge_cols, edge_vals, 0);
    }

    dot_kernel<<<(BATCH * 32 + 255) / 256, 256>>>(users, items, out);
}

// round 8
// speedup vs baseline: 1.2194x; 1.2194x over previous
#include <cuda_runtime.h>
#include <cuda_fp16.h>

#define NUM_USERS 50000
#define NUM_ITEMS 100000
#define NUM_NODES 150000   // NUM_USERS + NUM_ITEMS
#define LATENT_DIM 64
#define NNZ 4800000
#define BATCH 4096

// Scratch state (allocation-free, graph-capturable).
// Propagation buffers fp16 (128B/row) halve L2 gather traffic; acc stays fp32.
__device__ uint2 g_hA[NUM_NODES * LATENT_DIM / 4];   // 8B = 4 halfs per element
__device__ uint2 g_hB[NUM_NODES * LATENT_DIM / 4];
__device__ float g_acc[NUM_NODES * LATENT_DIM];
__device__ int   g_row_ptr[NUM_NODES + 1];

__device__ __forceinline__ unsigned h2_as_u32(__half2 h)
{
    return *reinterpret_cast<unsigned*>(&h);
}
__device__ __forceinline__ __half2 u32_as_h2(unsigned u)
{
    return *reinterpret_cast<__half2*>(&u);
}

__device__ __forceinline__ uint2 pack4(float a, float b, float c, float d)
{
    uint2 r;
    r.x = h2_as_u32(__floats2half2_rn(a, b));
    r.y = h2_as_u32(__floats2half2_rn(c, d));
    return r;
}

__device__ __forceinline__ void unpack4(uint2 p, float& a, float& b, float& c, float& d)
{
    float2 f0 = __half22float2(u32_as_h2(p.x));
    float2 f1 = __half22float2(u32_as_h2(p.y));
    a = f0.x; b = f0.y; c = f1.x; d = f1.y;
}

// ---------------------------------------------------------------------------
// Init: concat(user_emb, item_emb) -> g_hA (half, cur) and g_acc (fp32).
// One thread per 4 dims (one float4 in, one uint2 of halfs out).
// ---------------------------------------------------------------------------
__global__ void __launch_bounds__(256) init_kernel(const float4* __restrict__ user_emb,
                                                   const float4* __restrict__ item_emb)
{
    const int total  = NUM_NODES * LATENT_DIM / 4;
    const int uquads = NUM_USERS * LATENT_DIM / 4;
    int i = blockIdx.x * blockDim.x + threadIdx.x;
    if (i >= total) return;
    float4 v = (i < uquads) ? __ldg(&user_emb[i]) : __ldg(&item_emb[i - uquads]);
    reinterpret_cast<float4*>(g_acc)[i] = v;
    g_hA[i] = pack4(v.x, v.y, v.z, v.w);
}

// ---------------------------------------------------------------------------
// Build CSR row_ptr from sorted edge_rows.
// ---------------------------------------------------------------------------
__global__ void __launch_bounds__(256) rowptr_kernel(const int* __restrict__ rows)
{
    int e = blockIdx.x * blockDim.x + threadIdx.x;
    if (e >= NNZ) return;
    int r  = rows[e];
    int rp = (e == 0) ? -1 : rows[e - 1];
    for (int rr = rp + 1; rr <= r; ++rr) g_row_ptr[rr] = e;
    if (e == NNZ - 1) {
        for (int rr = r + 1; rr <= NUM_NODES; ++rr) g_row_ptr[rr] = NNZ;
    }
}

// ---------------------------------------------------------------------------
// SpMM (fp16 gather, fp32 accumulate): warp per row.
// Half-warp per edge, LDG.64: 16 lanes x uint2(8B = 4 halfs) = full 128B row,
// 2 edges per LDG instruction (2 lines/LDG — same bytes-per-LSU-slot as the
// fp32 R3 kernel that hit the LTS cap). 4 edges/iter, two load streams, small
// register footprint (s0[4]+s1[4]) to keep occupancy high.
// Metadata staged coalesced and shfl-broadcast; all shfl indices <= 31 by
// construction, out-of-range edges killed by zeroing v after the shfl.
// ---------------------------------------------------------------------------
__global__ void __launch_bounds__(256) spmm_kernel(const int*   __restrict__ cols,
                                                   const float* __restrict__ vals,
                                                   int flip)
{
    const uint2* __restrict__ xin  = flip ? g_hB : g_hA;
    uint2*       __restrict__ xout = flip ? g_hA : g_hB;

    const unsigned FULL = 0xffffffffu;
    int warp = (blockIdx.x * blockDim.x + threadIdx.x) >> 5;
    int lane = threadIdx.x & 31;
    if (warp >= NUM_NODES) return;

    const int start = g_row_ptr[warp];
    const int end   = g_row_ptr[warp + 1];

    const int sub = lane >> 4;      // edge slot (0/1) within a pair
    const int h   = lane & 15;      // 8B chunk within the 128B row

    const uint2* __restrict__ xq = xin + h;    // lane-fixed column (uint2 units)

    float s0[4] = {0.f, 0.f, 0.f, 0.f};
    float s1[4] = {0.f, 0.f, 0.f, 0.f};

    for (int base = start; base < end; base += 32) {
        const int n = min(32, end - base);      // warp-uniform
        int   c = 0;
        float v = 0.f;
        if (lane < n) {
            c = __ldg(&cols[base + lane]);
            v = __ldg(&vals[base + lane]);
        }

        for (int j = 0; j < n; j += 4) {        // warp-uniform; j <= 28
            const int e0 = j + sub;             // edges j, j+1     (<= 29)
            const int e1 = j + 2 + sub;         // edges j+2, j+3   (<= 31)

            int   cc0 = __shfl_sync(FULL, c, e0);
            int   cc1 = __shfl_sync(FULL, c, e1);
            float vv0 = __shfl_sync(FULL, v, e0);
            float vv1 = __shfl_sync(FULL, v, e1);
            if (e0 >= n) vv0 = 0.f;
            if (e1 >= n) vv1 = 0.f;

            uint2 x0 = __ldg(&xq[(size_t)cc0 * 16]);
            uint2 x1 = __ldg(&xq[(size_t)cc1 * 16]);

            float a0, a1, a2, a3;
            unpack4(x0, a0, a1, a2, a3);
            s0[0] += vv0 * a0;  s0[1] += vv0 * a1;
            s0[2] += vv0 * a2;  s0[3] += vv0 * a3;

            unpack4(x1, a0, a1, a2, a3);
            s1[0] += vv1 * a0;  s1[1] += vv1 * a1;
            s1[2] += vv1 * a2;  s1[3] += vv1 * a3;
        }
    }

    // combine streams, then merge the two half-warp edge partials (same h)
    #pragma unroll
    for (int k = 0; k < 4; ++k) {
        float s = s0[k] + s1[k];
        s += __shfl_xor_sync(FULL, s, 16);
        s0[k] = s;     // all lanes hold row sums for dims h*4+k
    }

    if (sub == 0) {
        // 16 lanes x 8B = full 128B half row
        xout[(size_t)warp * 16 + h] = pack4(s0[0], s0[1], s0[2], s0[3]);
    } else {
        // 16 lanes x 16B = full 256B fp32 acc row: acc += cur
        float4* accp = reinterpret_cast<float4*>(g_acc) + (size_t)warp * 16 + h;
        float4 a = *accp;
        a.x += s0[0]; a.y += s0[1]; a.z += s0[2]; a.w += s0[3];
        *accp = a;
    }
}

// ---------------------------------------------------------------------------
// Final: gamma[b] = dot(acc[users[b]], acc[NUM_USERS+items[b]]) / 16
// ---------------------------------------------------------------------------
__global__ void __launch_bounds__(256) dot_kernel(const int* __restrict__ users,
                                                  const int* __restrict__ items,
                                                  float* __restrict__ out)
{
    int warp = (blockIdx.x * blockDim.x + threadIdx.x) >> 5;
    int lane = threadIdx.x & 31;
    if (warp >= BATCH) return;

    size_t u  = (size_t)users[warp];
    size_t it = (size_t)items[warp] + NUM_USERS;

    const float2* au = reinterpret_cast<const float2*>(g_acc + u  * LATENT_DIM);
    const float2* ai = reinterpret_cast<const float2*>(g_acc + it * LATENT_DIM);

    float2 a = au[lane];
    float2 b = ai[lane];
    float s = a.x * b.x + a.y * b.y;

    #pragma unroll
    for (int o = 16; o > 0; o >>= 1)
        s += __shfl_xor_sync(0xffffffffu, s, o);

    if (lane == 0) out[warp] = s * (1.0f / 16.0f);
}

// ---------------------------------------------------------------------------
extern "C" void kernel_launch(void* const* d_in, const int* in_sizes, int n_in,
                              void* d_out, int out_size)
{
    const float* user_emb  = (const float*)d_in[0];
    const float* item_emb  = (const float*)d_in[1];
    const int*   edge_rows = (const int*)  d_in[2];
    const int*   edge_cols = (const int*)  d_in[3];
    const float* edge_vals = (const float*)d_in[4];
    const int*   users     = (const int*)  d_in[5];
    const int*   items     = (const int*)  d_in[6];
    float*       out       = (float*)d_out;

    (void)in_sizes; (void)n_in; (void)out_size;

    {
        int total = NUM_NODES * LATENT_DIM / 4;
        init_kernel<<<(total + 255) / 256, 256>>>(
            reinterpret_cast<const float4*>(user_emb),
            reinterpret_cast<const float4*>(item_emb));
    }

    rowptr_kernel<<<(NNZ + 255) / 256, 256>>>(edge_rows);

    {
        int blocks = (NUM_NODES * 32 + 255) / 256;   // warp per row
        spmm_kernel<<<blocks, 256>>>(edge_cols, edge_vals, 0);
        spmm_kernel<<<blocks, 256>>>(edge_cols, edge_vals, 1);
        spmm_kernel<<<blocks, 256>>>(edge_cols, edge_vals, 0);
    }

    dot_kernel<<<(BATCH * 32 + 255) / 256, 256>>>(users, items, out);
}

// round 9
// speedup vs baseline: 1.2288x; 1.0077x over previous
#include <cuda_runtime.h>
#include <cuda_fp16.h>

#define NUM_USERS 50000
#define NUM_ITEMS 100000
#define NUM_NODES 150000   // NUM_USERS + NUM_ITEMS
#define LATENT_DIM 64
#define NNZ 4800000
#define BATCH 4096

// Scratch state (allocation-free, graph-capturable).
// Propagation buffers fp16 (128B/row = 32 half2); acc stays fp32.
__device__ unsigned g_hA[NUM_NODES * 32];   // 4B = 1 half2 (2 dims) per element
__device__ unsigned g_hB[NUM_NODES * 32];
__device__ float    g_acc[NUM_NODES * LATENT_DIM];
__device__ int      g_row_ptr[NUM_NODES + 1];

__device__ __forceinline__ unsigned h2_as_u32(__half2 h)
{
    return *reinterpret_cast<unsigned*>(&h);
}
__device__ __forceinline__ __half2 u32_as_h2(unsigned u)
{
    return *reinterpret_cast<__half2*>(&u);
}

// ---------------------------------------------------------------------------
// Init: concat(user_emb, item_emb) -> g_hA (half, cur) and g_acc (fp32).
// One thread per 4 dims (one float4 in, two half2 out).
// ---------------------------------------------------------------------------
__global__ void __launch_bounds__(256) init_kernel(const float4* __restrict__ user_emb,
                                                   const float4* __restrict__ item_emb)
{
    const int total  = NUM_NODES * LATENT_DIM / 4;
    const int uquads = NUM_USERS * LATENT_DIM / 4;
    int i = blockIdx.x * blockDim.x + threadIdx.x;
    if (i >= total) return;
    float4 v = (i < uquads) ? __ldg(&user_emb[i]) : __ldg(&item_emb[i - uquads]);
    reinterpret_cast<float4*>(g_acc)[i] = v;
    uint2 p;
    p.x = h2_as_u32(__floats2half2_rn(v.x, v.y));
    p.y = h2_as_u32(__floats2half2_rn(v.z, v.w));
    reinterpret_cast<uint2*>(g_hA)[i] = p;
}

// ---------------------------------------------------------------------------
// Build CSR row_ptr from sorted edge_rows.
// ---------------------------------------------------------------------------
__global__ void __launch_bounds__(256) rowptr_kernel(const int* __restrict__ rows)
{
    int e = blockIdx.x * blockDim.x + threadIdx.x;
    if (e >= NNZ) return;
    int r  = rows[e];
    int rp = (e == 0) ? -1 : rows[e - 1];
    for (int rr = rp + 1; rr <= r; ++rr) g_row_ptr[rr] = e;
    if (e == NNZ - 1) {
        for (int rr = r + 1; rr <= NUM_NODES; ++rr) g_row_ptr[rr] = NNZ;
    }
}

// ---------------------------------------------------------------------------
// SpMM (fp16 gather, fp32 accumulate): warp per row, FULL WARP PER EDGE.
// Lane L permanently owns dims (2L, 2L+1): gather = one half2 (LDG.32,
// 32 lanes x 4B = whole 128B row = 1 L1 wavefront per edge), accumulator is
// a single float2, and there is NO cross-lane reduction.
// The 8-wide unrolled inner loop issues 8 shfl->LDG chains back-to-back
// (8 outstanding gathers per warp) before consuming them with FMAs —
// this is the MLP that hides the ~260cyc L2 hit latency.
// Metadata staged coalesced (one (col,val) per lane per 32-edge chunk);
// shfl index j+k <= 31 by construction; out-of-range edges killed by
// zeroing v after the shfl (their col defaults to 0 -> valid dead gather).
// ---------------------------------------------------------------------------
__global__ void __launch_bounds__(256) spmm_kernel(const int*   __restrict__ cols,
                                                   const float* __restrict__ vals,
                                                   int flip)
{
    const unsigned* __restrict__ xin  = flip ? g_hB : g_hA;
    unsigned*       __restrict__ xout = flip ? g_hA : g_hB;

    const unsigned FULL = 0xffffffffu;
    int warp = (blockIdx.x * blockDim.x + threadIdx.x) >> 5;
    int lane = threadIdx.x & 31;
    if (warp >= NUM_NODES) return;

    const int start = g_row_ptr[warp];
    const int end   = g_row_ptr[warp + 1];

    const unsigned* __restrict__ xq = xin + lane;   // lane-fixed half2 column

    float2 s = make_float2(0.f, 0.f);

    for (int base = start; base < end; base += 32) {
        const int n = min(32, end - base);          // warp-uniform
        int   c = 0;
        float v = 0.f;
        if (lane < n) {
            c = __ldg(&cols[base + lane]);
            v = __ldg(&vals[base + lane]);
        }

        for (int j = 0; j < n; j += 8) {            // j in {0,8,16,24}
            unsigned x[8];
            float    vv[8];
            #pragma unroll
            for (int k = 0; k < 8; ++k) {           // j+k <= 31: no mask needed
                int cc = __shfl_sync(FULL, c, j + k);
                vv[k]  = __shfl_sync(FULL, v, j + k);
                if (j + k >= n) vv[k] = 0.f;
                x[k] = __ldg(&xq[(size_t)cc * 32]); // 8 gathers in flight
            }
            #pragma unroll
            for (int k = 0; k < 8; ++k) {
                float2 f = __half22float2(u32_as_h2(x[k]));
                s.x += vv[k] * f.x;
                s.y += vv[k] * f.y;
            }
        }
    }

    // lane L writes dims (2L, 2L+1) everywhere — no reduction needed.
    xout[(size_t)warp * 32 + lane] = h2_as_u32(__floats2half2_rn(s.x, s.y));

    float2* accp = reinterpret_cast<float2*>(g_acc) + (size_t)warp * 32 + lane;
    float2 a = *accp;
    a.x += s.x;
    a.y += s.y;
    *accp = a;
}

// ---------------------------------------------------------------------------
// Final: gamma[b] = dot(acc[users[b]], acc[NUM_USERS+items[b]]) / 16
// ---------------------------------------------------------------------------
__global__ void __launch_bounds__(256) dot_kernel(const int* __restrict__ users,
                                                  const int* __restrict__ items,
                                                  float* __restrict__ out)
{
    int warp = (blockIdx.x * blockDim.x + threadIdx.x) >> 5;
    int lane = threadIdx.x & 31;
    if (warp >= BATCH) return;

    size_t u  = (size_t)users[warp];
    size_t it = (size_t)items[warp] + NUM_USERS;

    const float2* au = reinterpret_cast<const float2*>(g_acc + u  * LATENT_DIM);
    const float2* ai = reinterpret_cast<const float2*>(g_acc + it * LATENT_DIM);

    float2 a = au[lane];
    float2 b = ai[lane];
    float s = a.x * b.x + a.y * b.y;

    #pragma unroll
    for (int o = 16; o > 0; o >>= 1)
        s += __shfl_xor_sync(0xffffffffu, s, o);

    if (lane == 0) out[warp] = s * (1.0f / 16.0f);
}

// ---------------------------------------------------------------------------
extern "C" void kernel_launch(void* const* d_in, const int* in_sizes, int n_in,
                              void* d_out, int out_size)
{
    const float* user_emb  = (const float*)d_in[0];
    const float* item_emb  = (const float*)d_in[1];
    const int*   edge_rows = (const int*)  d_in[2];
    const int*   edge_cols = (const int*)  d_in[3];
    const float* edge_vals = (const float*)d_in[4];
    const int*   users     = (const int*)  d_in[5];
    const int*   items     = (const int*)  d_in[6];
    float*       out       = (float*)d_out;

    (void)in_sizes; (void)n_in; (void)out_size;

    {
        int total = NUM_NODES * LATENT_DIM / 4;
        init_kernel<<<(total + 255) / 256, 256>>>(
            reinterpret_cast<const float4*>(user_emb),
            reinterpret_cast<const float4*>(item_emb));
    }

    rowptr_kernel<<<(NNZ + 255) / 256, 256>>>(edge_rows);

    {
        int blocks = (NUM_NODES * 32 + 255) / 256;   // warp per row
        spmm_kernel<<<blocks, 256>>>(edge_cols, edge_vals, 0);
        spmm_kernel<<<blocks, 256>>>(edge_cols, edge_vals, 1);
        spmm_kernel<<<blocks, 256>>>(edge_cols, edge_vals, 0);
    }

    dot_kernel<<<(BATCH * 32 + 255) / 256, 256>>>(users, items, out);
}

// round 10
// speedup vs baseline: 1.3410x; 1.0913x over previous
#include <cuda_runtime.h>
#include <cuda_fp16.h>

#define NUM_USERS 50000
#define NUM_ITEMS 100000
#define NUM_NODES 150000   // NUM_USERS + NUM_ITEMS
#define LATENT_DIM 64
#define NNZ 4800000
#define BATCH 4096

// Scratch (allocation-free, graph-capturable). Four fp16 buffers: h0 = input
// embeddings, h1..h3 = per-layer SpMM outputs (128B/row = 32 half2 each).
// No running accumulator: the final dot reconstructs acc = e0+e1+e2+e3 for
// just the sampled nodes (e0 read from the fp32 inputs directly).
__device__ unsigned g_h0[NUM_NODES * 32];
__device__ unsigned g_h1[NUM_NODES * 32];
__device__ unsigned g_h2[NUM_NODES * 32];
__device__ unsigned g_h3[NUM_NODES * 32];
__device__ int      g_row_ptr[NUM_NODES + 1];

__device__ __forceinline__ unsigned h2_as_u32(__half2 h)
{
    return *reinterpret_cast<unsigned*>(&h);
}
__device__ __forceinline__ __half2 u32_as_h2(unsigned u)
{
    return *reinterpret_cast<__half2*>(&u);
}

// ---------------------------------------------------------------------------
// Init: concat(user_emb, item_emb) -> g_h0 (fp16). One thread per 4 dims.
// ---------------------------------------------------------------------------
__global__ void __launch_bounds__(256) init_kernel(const float4* __restrict__ user_emb,
                                                   const float4* __restrict__ item_emb)
{
    const int total  = NUM_NODES * LATENT_DIM / 4;
    const int uquads = NUM_USERS * LATENT_DIM / 4;
    int i = blockIdx.x * blockDim.x + threadIdx.x;
    if (i >= total) return;
    float4 v = (i < uquads) ? __ldg(&user_emb[i]) : __ldg(&item_emb[i - uquads]);
    uint2 p;
    p.x = h2_as_u32(__floats2half2_rn(v.x, v.y));
    p.y = h2_as_u32(__floats2half2_rn(v.z, v.w));
    reinterpret_cast<uint2*>(g_h0)[i] = p;
}

// ---------------------------------------------------------------------------
// Build CSR row_ptr from sorted edge_rows.
// ---------------------------------------------------------------------------
__global__ void __launch_bounds__(256) rowptr_kernel(const int* __restrict__ rows)
{
    int e = blockIdx.x * blockDim.x + threadIdx.x;
    if (e >= NNZ) return;
    int r  = rows[e];
    int rp = (e == 0) ? -1 : rows[e - 1];
    for (int rr = rp + 1; rr <= r; ++rr) g_row_ptr[rr] = e;
    if (e == NNZ - 1) {
        for (int rr = r + 1; rr <= NUM_NODES; ++rr) g_row_ptr[rr] = NNZ;
    }
}

// ---------------------------------------------------------------------------
// SpMM (fp16 gather, fp32 accumulate): warp per row, full warp per edge.
// Lane L owns dims (2L, 2L+1): gather = one half2 LDG.32 (whole 128B row per
// warp, 1 L1 wavefront/edge), single float2 accumulator, no reduction.
// Edge metadata staged per 32-edge chunk into shared memory as int2
// (2 coalesced LDG + 1 STS), then read back with one broadcast LDS.64 per
// edge — replaces the 2 shfl + 2 predicate ops of the previous version.
// The stage zero-fills entries past n, so the 8-wide unrolled inner loop is
// completely branchless (dead edges gather row 0 with val 0).
// Per full-chunk edge: 1 LDS.64 + 1 IMAD + 1 LDG.32 + 2 CVT + 2 FFMA.
// ---------------------------------------------------------------------------
__global__ void __launch_bounds__(256) spmm_kernel(const int*   __restrict__ cols,
                                                   const float* __restrict__ vals,
                                                   int which)
{
    __shared__ int2 meta[8][32];     // 8 warps/block x 32 staged edges (2KB)

    const unsigned* __restrict__ xin;
    unsigned*       __restrict__ xout;
    if (which == 0)      { xin = g_h0; xout = g_h1; }
    else if (which == 1) { xin = g_h1; xout = g_h2; }
    else                 { xin = g_h2; xout = g_h3; }

    int warp = (blockIdx.x * blockDim.x + threadIdx.x) >> 5;
    int lane = threadIdx.x & 31;
    int wib  = (threadIdx.x >> 5);
    if (warp >= NUM_NODES) return;

    const int start = g_row_ptr[warp];
    const int end   = g_row_ptr[warp + 1];

    const unsigned* __restrict__ xq = xin + lane;   // lane-fixed half2 column
    int2* mrow = meta[wib];

    float2 s = make_float2(0.f, 0.f);

    for (int base = start; base < end; base += 32) {
        const int n = min(32, end - base);          // warp-uniform
        int2 m = make_int2(0, 0);                   // zero-pad: col 0, val 0
        if (lane < n)
            m = make_int2(__ldg(&cols[base + lane]),
                          __float_as_int(__ldg(&vals[base + lane])));
        __syncwarp();                               // protect prior chunk reads
        mrow[lane] = m;
        __syncwarp();

        const int mcount = (n + 7) & ~7;            // branchless padded count
        for (int j = 0; j < mcount; j += 8) {
            #pragma unroll
            for (int k = 0; k < 8; ++k) {           // 8 gathers in flight
                int2 e = mrow[j + k];               // broadcast LDS.64
                unsigned x = __ldg(&xq[(size_t)e.x * 32]);
                float vv = __int_as_float(e.y);
                float2 f = __half22float2(u32_as_h2(x));
                s.x += vv * f.x;
                s.y += vv * f.y;
            }
        }
    }

    // lane L writes dims (2L, 2L+1); zeros for empty rows (correct: segment_sum)
    xout[(size_t)warp * 32 + lane] = h2_as_u32(__floats2half2_rn(s.x, s.y));
}

// ---------------------------------------------------------------------------
// Final: for each batch element, reconstruct acc = e0+e1+e2+e3 for the two
// sampled nodes (e0 from fp32 inputs, e1..e3 from fp16 layer buffers), dot,
// divide by 16 (the two /4 layer norms folded).  Warp per element; lane L
// owns dims (2L, 2L+1).
// ---------------------------------------------------------------------------
__global__ void __launch_bounds__(256) dot_kernel(const float2* __restrict__ user_emb,
                                                  const float2* __restrict__ item_emb,
                                                  const int*    __restrict__ users,
                                                  const int*    __restrict__ items,
                                                  float* __restrict__ out)
{
    int warp = (blockIdx.x * blockDim.x + threadIdx.x) >> 5;
    int lane = threadIdx.x & 31;
    if (warp >= BATCH) return;

    const int u  = users[warp];
    const int it = items[warp];
    const size_t un = (size_t)u;                   // node id of user
    const size_t in = (size_t)it + NUM_USERS;      // node id of item

    // user side: e0 + e1 + e2 + e3 at dims (2L, 2L+1)
    float2 ua = __ldg(&user_emb[(size_t)u * 32 + lane]);
    {
        float2 f1 = __half22float2(u32_as_h2(__ldg(&g_h1[un * 32 + lane])));
        float2 f2 = __half22float2(u32_as_h2(__ldg(&g_h2[un * 32 + lane])));
        float2 f3 = __half22float2(u32_as_h2(__ldg(&g_h3[un * 32 + lane])));
        ua.x += f1.x + f2.x + f3.x;
        ua.y += f1.y + f2.y + f3.y;
    }

    // item side
    float2 ia = __ldg(&item_emb[(size_t)it * 32 + lane]);
    {
        float2 f1 = __half22float2(u32_as_h2(__ldg(&g_h1[in * 32 + lane])));
        float2 f2 = __half22float2(u32_as_h2(__ldg(&g_h2[in * 32 + lane])));
        float2 f3 = __half22float2(u32_as_h2(__ldg(&g_h3[in * 32 + lane])));
        ia.x += f1.x + f2.x + f3.x;
        ia.y += f1.y + f2.y + f3.y;
    }

    float s = ua.x * ia.x + ua.y * ia.y;

    #pragma unroll
    for (int o = 16; o > 0; o >>= 1)
        s += __shfl_xor_sync(0xffffffffu, s, o);

    if (lane == 0) out[warp] = s * (1.0f / 16.0f);
}

// ---------------------------------------------------------------------------
extern "C" void kernel_launch(void* const* d_in, const int* in_sizes, int n_in,
                              void* d_out, int out_size)
{
    const float* user_emb  = (const float*)d_in[0];
    const float* item_emb  = (const float*)d_in[1];
    const int*   edge_rows = (const int*)  d_in[2];
    const int*   edge_cols = (const int*)  d_in[3];
    const float* edge_vals = (const float*)d_in[4];
    const int*   users     = (const int*)  d_in[5];
    const int*   items     = (const int*)  d_in[6];
    float*       out       = (float*)d_out;

    (void)in_sizes; (void)n_in; (void)out_size;

    {
        int total = NUM_NODES * LATENT_DIM / 4;
        init_kernel<<<(total + 255) / 256, 256>>>(
            reinterpret_cast<const float4*>(user_emb),
            reinterpret_cast<const float4*>(item_emb));
    }

    rowptr_kernel<<<(NNZ + 255) / 256, 256>>>(edge_rows);

    {
        int blocks = (NUM_NODES * 32 + 255) / 256;   // warp per row
        spmm_kernel<<<blocks, 256>>>(edge_cols, edge_vals, 0);  // h0 -> h1
        spmm_kernel<<<blocks, 256>>>(edge_cols, edge_vals, 1);  // h1 -> h2
        spmm_kernel<<<blocks, 256>>>(edge_cols, edge_vals, 2);  // h2 -> h3
    }

    dot_kernel<<<(BATCH * 32 + 255) / 256, 256>>>(
        reinterpret_cast<const float2*>(user_emb),
        reinterpret_cast<const float2*>(item_emb),
        users, items, out);
}

// round 11
// speedup vs baseline: 1.8371x; 1.3699x over previous
#include <cuda_runtime.h>
#include <cuda_fp16.h>

#define NUM_USERS 50000
#define NUM_ITEMS 100000
#define NUM_NODES 150000   // NUM_USERS + NUM_ITEMS
#define LATENT_DIM 64
#define NNZ 4800000
#define BATCH 4096

// Scratch (allocation-free, graph-capturable). fp16 buffers: h0 = input
// embeddings, h1/h2 = layer outputs (128B/row = 32 half2 each).
// Layer 3 is never materialized: it is computed on the fly in the dot kernel
// for just the sampled nodes.
__device__ unsigned g_h0[NUM_NODES * 32];
__device__ unsigned g_h1[NUM_NODES * 32];
__device__ unsigned g_h2[NUM_NODES * 32];
__device__ int      g_row_ptr[NUM_NODES + 1];

__device__ __forceinline__ unsigned h2_as_u32(__half2 h)
{
    return *reinterpret_cast<unsigned*>(&h);
}
__device__ __forceinline__ __half2 u32_as_h2(unsigned u)
{
    return *reinterpret_cast<__half2*>(&u);
}

// ---------------------------------------------------------------------------
// Init: concat(user_emb, item_emb) -> g_h0 (fp16). One thread per 4 dims.
// ---------------------------------------------------------------------------
__global__ void __launch_bounds__(256) init_kernel(const float4* __restrict__ user_emb,
                                                   const float4* __restrict__ item_emb)
{
    const int total  = NUM_NODES * LATENT_DIM / 4;
    const int uquads = NUM_USERS * LATENT_DIM / 4;
    int i = blockIdx.x * blockDim.x + threadIdx.x;
    if (i >= total) return;
    float4 v = (i < uquads) ? __ldg(&user_emb[i]) : __ldg(&item_emb[i - uquads]);
    uint2 p;
    p.x = h2_as_u32(__floats2half2_rn(v.x, v.y));
    p.y = h2_as_u32(__floats2half2_rn(v.z, v.w));
    reinterpret_cast<uint2*>(g_h0)[i] = p;
}

// ---------------------------------------------------------------------------
// Build CSR row_ptr from sorted edge_rows.
// ---------------------------------------------------------------------------
__global__ void __launch_bounds__(256) rowptr_kernel(const int* __restrict__ rows)
{
    int e = blockIdx.x * blockDim.x + threadIdx.x;
    if (e >= NNZ) return;
    int r  = rows[e];
    int rp = (e == 0) ? -1 : rows[e - 1];
    for (int rr = rp + 1; rr <= r; ++rr) g_row_ptr[rr] = e;
    if (e == NNZ - 1) {
        for (int rr = r + 1; rr <= NUM_NODES; ++rr) g_row_ptr[rr] = NNZ;
    }
}

// ---------------------------------------------------------------------------
// SpMM (fp16 gather, fp32 accumulate): warp per TWO consecutive rows.
// Rows 2w and 2w+1 are contiguous in the sorted edge array, so one staged
// 32-edge span serves both. At stage time each edge's val is steered into
// the row-A or row-B slot of an int4 {col, vA, vB, 0}; the branchless inner
// loop does 1 LDS.128 + 1 LDG.32 + 2 CVT + 4 FFMA per edge, maintaining two
// independent accumulation chains per warp (2x the latency-hiding window of
// the one-row version). Lane L owns dims (2L, 2L+1); no cross-lane reduce.
// ---------------------------------------------------------------------------
__global__ void __launch_bounds__(256) spmm_kernel(const int*   __restrict__ cols,
                                                   const float* __restrict__ vals,
                                                   int which)
{
    __shared__ int4 meta[8][32];     // 8 warps/block x 32 staged edges (4KB)

    const unsigned* __restrict__ xin  = (which == 0) ? g_h0 : g_h1;
    unsigned*       __restrict__ xout = (which == 0) ? g_h1 : g_h2;

    int warp = (blockIdx.x * blockDim.x + threadIdx.x) >> 5;
    int lane = threadIdx.x & 31;
    int wib  = (threadIdx.x >> 5);
    if (warp >= NUM_NODES / 2) return;

    const int r0 = warp * 2;
    const int pA = g_row_ptr[r0];
    const int pM = g_row_ptr[r0 + 1];
    const int pB = g_row_ptr[r0 + 2];

    const unsigned* __restrict__ xq = xin + lane;   // lane-fixed half2 column
    int4* mrow = meta[wib];

    float2 sA = make_float2(0.f, 0.f);
    float2 sB = make_float2(0.f, 0.f);

    for (int base = pA; base < pB; base += 32) {
        const int n = min(32, pB - base);           // warp-uniform
        int4 m = make_int4(0, 0, 0, 0);             // zero-pad: col 0, vals 0
        if (lane < n) {
            const int e = base + lane;
            const int c = __ldg(&cols[e]);
            const int v = __float_as_int(__ldg(&vals[e]));
            const bool isA = (e < pM);
            m = make_int4(c, isA ? v : 0, isA ? 0 : v, 0);
        }
        __syncwarp();                               // prior chunk reads done
        mrow[lane] = m;
        __syncwarp();

        const int mcount = (n + 7) & ~7;            // branchless padded count
        for (int j = 0; j < mcount; j += 8) {
            #pragma unroll
            for (int k = 0; k < 8; ++k) {           // 8 gathers in flight
                int4 e = mrow[j + k];               // broadcast LDS.128
                unsigned x = __ldg(&xq[(size_t)e.x * 32]);
                float vA = __int_as_float(e.y);
                float vB = __int_as_float(e.z);
                float2 f = __half22float2(u32_as_h2(x));
                sA.x += vA * f.x;  sA.y += vA * f.y;
                sB.x += vB * f.x;  sB.y += vB * f.y;
            }
        }
    }

    xout[(size_t)r0 * 32 + lane]       = h2_as_u32(__floats2half2_rn(sA.x, sA.y));
    xout[(size_t)(r0 + 1) * 32 + lane] = h2_as_u32(__floats2half2_rn(sB.x, sB.y));
}

// ---------------------------------------------------------------------------
// Compute one layer-3 row on the fly: e3[node] = sum vals * h2[cols] at
// dims (2L, 2L+1). Shfl-staged metadata (small row counts; 8192 rows total).
// ---------------------------------------------------------------------------
__device__ __forceinline__ float2 spmm_row_h2(const int*   __restrict__ cols,
                                              const float* __restrict__ vals,
                                              int node, int lane)
{
    const unsigned FULL = 0xffffffffu;
    const int start = g_row_ptr[node];
    const int end   = g_row_ptr[node + 1];
    const unsigned* __restrict__ xq = g_h2 + lane;

    float2 s = make_float2(0.f, 0.f);
    for (int base = start; base < end; base += 32) {
        const int n = min(32, end - base);
        int   c = 0;
        float v = 0.f;
        if (lane < n) {
            c = __ldg(&cols[base + lane]);
            v = __ldg(&vals[base + lane]);
        }
        for (int j = 0; j < n; j += 8) {
            #pragma unroll
            for (int k = 0; k < 8; ++k) {           // j+k <= 31
                int   cc = __shfl_sync(FULL, c, j + k);
                float vv = __shfl_sync(FULL, v, j + k);
                if (j + k >= n) vv = 0.f;
                unsigned x = __ldg(&xq[(size_t)cc * 32]);
                float2 f = __half22float2(u32_as_h2(x));
                s.x += vv * f.x;
                s.y += vv * f.y;
            }
        }
    }
    return s;
}

// ---------------------------------------------------------------------------
// Fused layer-3 + dot: for each batch element, compute e3 for its two nodes
// directly from h2 (fp32, never rounded), reconstruct acc = e0+e1+e2+e3,
// dot, /16 (the two /4 layer norms folded). Warp per element; lane L owns
// dims (2L, 2L+1).
// ---------------------------------------------------------------------------
__global__ void __launch_bounds__(256) dot_kernel(const float2* __restrict__ user_emb,
                                                  const float2* __restrict__ item_emb,
                                                  const int*    __restrict__ users,
                                                  const int*    __restrict__ items,
                                                  const int*    __restrict__ cols,
                                                  const float*  __restrict__ vals,
                                                  float* __restrict__ out)
{
    int warp = (blockIdx.x * blockDim.x + threadIdx.x) >> 5;
    int lane = threadIdx.x & 31;
    if (warp >= BATCH) return;

    const int u  = users[warp];
    const int it = items[warp];
    const int un = u;                       // user node id
    const int in = it + NUM_USERS;          // item node id

    // user side: acc = e0 + e1 + e2 + e3
    float2 ua = __ldg(&user_emb[(size_t)u * 32 + lane]);
    {
        float2 f1 = __half22float2(u32_as_h2(__ldg(&g_h1[(size_t)un * 32 + lane])));
        float2 f2 = __half22float2(u32_as_h2(__ldg(&g_h2[(size_t)un * 32 + lane])));
        float2 f3 = spmm_row_h2(cols, vals, un, lane);
        ua.x += f1.x + f2.x + f3.x;
        ua.y += f1.y + f2.y + f3.y;
    }

    // item side
    float2 ia = __ldg(&item_emb[(size_t)it * 32 + lane]);
    {
        float2 f1 = __half22float2(u32_as_h2(__ldg(&g_h1[(size_t)in * 32 + lane])));
        float2 f2 = __half22float2(u32_as_h2(__ldg(&g_h2[(size_t)in * 32 + lane])));
        float2 f3 = spmm_row_h2(cols, vals, in, lane);
        ia.x += f1.x + f2.x + f3.x;
        ia.y += f1.y + f2.y + f3.y;
    }

    float s = ua.x * ia.x + ua.y * ia.y;

    #pragma unroll
    for (int o = 16; o > 0; o >>= 1)
        s += __shfl_xor_sync(0xffffffffu, s, o);

    if (lane == 0) out[warp] = s * (1.0f / 16.0f);
}

// ---------------------------------------------------------------------------
extern "C" void kernel_launch(void* const* d_in, const int* in_sizes, int n_in,
                              void* d_out, int out_size)
{
    const float* user_emb  = (const float*)d_in[0];
    const float* item_emb  = (const float*)d_in[1];
    const int*   edge_rows = (const int*)  d_in[2];
    const int*   edge_cols = (const int*)  d_in[3];
    const float* edge_vals = (const float*)d_in[4];
    const int*   users     = (const int*)  d_in[5];
    const int*   items     = (const int*)  d_in[6];
    float*       out       = (float*)d_out;

    (void)in_sizes; (void)n_in; (void)out_size;

    {
        int total = NUM_NODES * LATENT_DIM / 4;
        init_kernel<<<(total + 255) / 256, 256>>>(
            reinterpret_cast<const float4*>(user_emb),
            reinterpret_cast<const float4*>(item_emb));
    }

    rowptr_kernel<<<(NNZ + 255) / 256, 256>>>(edge_rows);

    {
        // warp per 2 rows: 75000 warps
        int blocks = (NUM_NODES / 2 * 32 + 255) / 256;
        spmm_kernel<<<blocks, 256>>>(edge_cols, edge_vals, 0);  // h0 -> h1
        spmm_kernel<<<blocks, 256>>>(edge_cols, edge_vals, 1);  // h1 -> h2
    }

    dot_kernel<<<(BATCH * 32 + 255) / 256, 256>>>(
        reinterpret_cast<const float2*>(user_emb),
        reinterpret_cast<const float2*>(item_emb),
        users, items, edge_cols, edge_vals, out);
}